// round 13
// baseline (speedup 1.0000x reference)
#include <cuda_runtime.h>

#define NP 768
#define CC 128
#define TILE 128
#define NTILES (NP / TILE)    // 6 n-tiles per CTA
#define L2E 1.4426950408889634f

// Quartic polynomial coefficients (from precompute): [o][monomial j][channel]
__device__ float g_P[2][35][CC];
// Normalized per-(m,c) softmax aggregates: [q in 0..2][m][c]
__device__ float g_norm[3][NP][CC];

// ---------------- f32x2 packed helpers (sm_103a) ----------------
typedef unsigned long long ull;
__device__ __forceinline__ ull pack2(float lo, float hi) {
    ull r;
    asm("mov.b64 %0, {%1,%2};" : "=l"(r) : "f"(lo), "f"(hi));
    return r;
}
__device__ __forceinline__ void unpack2(float& lo, float& hi, ull v) {
    asm("mov.b64 {%0,%1}, %2;" : "=f"(lo), "=f"(hi) : "l"(v));
}
__device__ __forceinline__ ull ffma2(ull a, ull b, ull c) {
    ull d;
    asm("fma.rn.f32x2 %0, %1, %2, %3;" : "=l"(d) : "l"(a), "l"(b), "l"(c));
    return d;
}
__device__ __forceinline__ ull fmul2(ull a, ull b) {
    ull d;
    asm("mul.rn.f32x2 %0, %1, %2;" : "=l"(d) : "l"(a), "l"(b));
    return d;
}
// bare hardware exp2 (no libdevice fixups)
__device__ __forceinline__ float ex2(float x) {
    float y;
    asm("ex2.approx.ftz.f32 %0, %1;" : "=f"(y) : "f"(x));
    return y;
}

// ---------------------------------------------------------------------------
// Precompute v2: one CTA, 512 threads = 128 channels x 4 segments.
// Layer 2: k-split (4 x 32-k segments), W2 rows loaded directly via LDG.128
//          (128KB, L1-resident), sV broadcast from smem; one smem combine.
// Layer 3: j-split (4 x 9 coefficients), full k-loop per thread, W3 rows via
//          LDG.128 (L1-hot), sE broadcast from smem; no combine needed.
// Monomials (35): a=0..4 (d), b=0..4-a (u), c=0..4-a-b (v), lexicographic.
// ---------------------------------------------------------------------------
__global__ void __launch_bounds__(512) precompute_kernel(
    const float* __restrict__ Wa1, const float* __restrict__ ba1,
    const float* __restrict__ Wb1, const float* __restrict__ bb1,
    const float* __restrict__ Wa2, const float* __restrict__ ba2,
    const float* __restrict__ Wb2, const float* __restrict__ bb2,
    const float* __restrict__ Wa3, const float* __restrict__ ba3,
    const float* __restrict__ Wb3, const float* __restrict__ bb3)
{
    __shared__ float sV[CC][10];        // layer-1 pair-product quadratics
    __shared__ float sBuf[CC * 80];     // 40KB: sQ[c][seg][20] then sE[k][36]
    __shared__ int sLUT[125];
    const int t = threadIdx.x;
    const int c = t & 127;
    const int seg = t >> 7;             // 0..3

    if (t == 0) {
        int j = 0;
        for (int a = 0; a <= 4; ++a)
            for (int b = 0; b <= 4 - a; ++b)
                for (int cc = 0; cc <= 4 - a - b; ++cc)
                    sLUT[a * 25 + b * 5 + cc] = j++;
    }
    if (seg == 0) {
        // Layer-1 homogeneous vectors over g = (d,u,v,1) -> pairwise products
        float A0 = Wa1[3*c], A1 = Wa1[3*c+1], A2 = Wa1[3*c+2], A3 = ba1[c];
        float B0 = Wb1[3*c], B1 = Wb1[3*c+1], B2 = Wb1[3*c+2], B3 = bb1[c];
        sV[c][0] = A0*B0;
        sV[c][1] = A0*B1 + A1*B0;
        sV[c][2] = A0*B2 + A2*B0;
        sV[c][3] = A0*B3 + A3*B0;
        sV[c][4] = A1*B1;
        sV[c][5] = A1*B2 + A2*B1;
        sV[c][6] = A1*B3 + A3*B1;
        sV[c][7] = A2*B2;
        sV[c][8] = A2*B3 + A3*B2;
        sV[c][9] = A3*B3;
    }
    __syncthreads();

    // ---- Layer 2: partial quadratic forms over this thread's 32-k segment ----
    float qa[10], qb[10];
    #pragma unroll
    for (int p = 0; p < 10; ++p) { qa[p] = 0.f; qb[p] = 0.f; }
    {
        const float4* wa4 = (const float4*)(Wa2 + c * CC + seg * 32);
        const float4* wb4 = (const float4*)(Wb2 + c * CC + seg * 32);
        #pragma unroll
        for (int q4 = 0; q4 < 8; ++q4) {
            float4 wa = __ldg(wa4 + q4);
            float4 wb = __ldg(wb4 + q4);
            int kb = seg * 32 + q4 * 4;
            float was[4] = {wa.x, wa.y, wa.z, wa.w};
            float wbs[4] = {wb.x, wb.y, wb.z, wb.w};
            #pragma unroll
            for (int kk = 0; kk < 4; ++kk) {
                const float* vv = &sV[kb + kk][0];
                #pragma unroll
                for (int p = 0; p < 10; ++p) {
                    qa[p] = fmaf(was[kk], vv[p], qa[p]);
                    qb[p] = fmaf(wbs[kk], vv[p], qb[p]);
                }
            }
        }
    }
    // combine the 4 segment partials through sBuf (sQ view: [c][seg][20])
    {
        float* sQ = &sBuf[(c * 4 + seg) * 20];
        #pragma unroll
        for (int p = 0; p < 10; ++p) { sQ[p] = qa[p]; sQ[10 + p] = qb[p]; }
    }
    __syncthreads();

    float e[35];                         // expansion kept in registers (seg 0)
    if (seg == 0) {
        #pragma unroll
        for (int p = 0; p < 10; ++p) { qa[p] = 0.f; qb[p] = 0.f; }
        #pragma unroll
        for (int s = 0; s < 4; ++s) {
            const float* sQ = &sBuf[(c * 4 + s) * 20];
            #pragma unroll
            for (int p = 0; p < 10; ++p) { qa[p] += sQ[p]; qb[p] += sQ[10 + p]; }
        }
        qa[9] += ba2[c];                 // bias = constant monomial
        qb[9] += bb2[c];
        // h2[c] = Qa * Qb -> quartic expansion (35 coefficients)
        #pragma unroll
        for (int j = 0; j < 35; ++j) e[j] = 0.f;
        const int pk[10] = {50, 30, 26, 25, 10, 6, 5, 2, 1, 0};
        #pragma unroll
        for (int p = 0; p < 10; ++p) {
            float va = qa[p];
            #pragma unroll
            for (int q = 0; q < 10; ++q)
                e[sLUT[pk[p] + pk[q]]] += va * qb[q];
        }
    }
    __syncthreads();                      // all sQ reads done before overwrite
    if (seg == 0) {
        float* sErow = &sBuf[c * 36];     // sE view: [k][36]
        #pragma unroll
        for (int j = 0; j < 35; ++j) sErow[j] = e[j];
        sErow[35] = 0.f;                  // keep padding clean
    }
    __syncthreads();

    // ---- Layer 3: P = W3 @ E; thread (c, jg) owns 9 coefficients ----
    const int j0 = seg * 9;               // 0,9,18,27 (last group has 8 valid)
    const int nj = (seg == 3) ? 8 : 9;
    float pa[9], pb[9];
    #pragma unroll
    for (int j = 0; j < 9; ++j) { pa[j] = 0.f; pb[j] = 0.f; }
    {
        const float4* wa4 = (const float4*)(Wa3 + c * CC);
        const float4* wb4 = (const float4*)(Wb3 + c * CC);
        for (int q4 = 0; q4 < 32; ++q4) {
            float4 wa = __ldg(wa4 + q4);
            float4 wb = __ldg(wb4 + q4);
            int kb = q4 * 4;
            float was[4] = {wa.x, wa.y, wa.z, wa.w};
            float wbs[4] = {wb.x, wb.y, wb.z, wb.w};
            #pragma unroll
            for (int kk = 0; kk < 4; ++kk) {
                const float* ee = &sBuf[(kb + kk) * 36 + j0];
                #pragma unroll
                for (int j = 0; j < 9; ++j) {     // j==8 of seg3 hits padding 0
                    pa[j] = fmaf(was[kk], ee[j], pa[j]);
                    pb[j] = fmaf(wbs[kk], ee[j], pb[j]);
                }
            }
        }
    }
    if (seg == 0) {
        pa[0] += ba3[c];                  // bias on constant monomial j=0
        pb[0] += bb3[c];
    }
    for (int j = 0; j < nj; ++j) {
        g_P[0][j0 + j][c] = pa[j];
        g_P[1][j0 + j][c] = pb[j];
    }
}

// ---------------------------------------------------------------------------
// Main: one CTA per m. Thread = channel. Branchless ALWAYS-RESCALE online
// softmax (exact): with d = h - M, q = ex2(-|d|), exactly one of {rescale r,
// new term e} equals q and the other equals 1. All ex2 args <= 0 -> no
// overflow; D >= 1 after the first step -> no 0/0.
// ---------------------------------------------------------------------------
__global__ void __launch_bounds__(128, 5) fps_main_kernel(const float* __restrict__ x)
{
    // interleaved monomials: [pair nn][slot 0..13, pad to 18][even/odd]
    __shared__ __align__(16) float smP[TILE/2][18][2];
    __shared__ __align__(16) float smX[3][TILE];
    const int m = blockIdx.x;
    const int t = threadIdx.x;

    const float xm0 = x[3*m], xm1 = x[3*m+1], xm2 = x[3*m+2];
    const float um2 = fmaf(xm0, xm0, fmaf(xm1, xm1, xm2 * xm2));
    const float u = sqrtf(um2);

    // ---- prologue: fold u^b into coefficients, pack duplicated f32x2 ----
    float up[5];
    up[0] = 1.f; up[1] = u; up[2] = um2; up[3] = um2 * u; up[4] = um2 * um2;
    const int JB[35] = {0,0,0,0,0, 1,1,1,1, 2,2,2, 3,3, 4,
                        0,0,0,0, 1,1,1, 2,2, 3,
                        0,0,0, 1,1, 2,
                        0,0, 1, 0};
    const int JF[35] = {0,1,2,3,4, 0,1,2,3, 0,1,2, 0,1, 0,
                        5,6,7,8, 5,6,7, 5,6, 5,
                        9,10,11, 9,10, 9,
                        12,13, 12, 14};
    float paf[15], pbf[15];
    #pragma unroll
    for (int f = 0; f < 15; ++f) { paf[f] = 0.f; pbf[f] = 0.f; }
    #pragma unroll
    for (int j = 0; j < 35; ++j) {
        float ub = up[JB[j]];
        paf[JF[j]] = fmaf(g_P[0][j][t], ub, paf[JF[j]]);
        pbf[JF[j]] = fmaf(g_P[1][j][t], ub, pbf[JF[j]]);
    }
    ull paf2[15], pbf2[15];
    #pragma unroll
    for (int j = 0; j < 15; ++j) {
        float a = paf[j] * L2E;              // fold log2(e) into P_a
        paf2[j] = pack2(a, a);
        pbf2[j] = pack2(pbf[j], pbf[j]);
    }

    // ---- phase 1 for tile 0 ----
    {
        const int n = t;
        float xn0 = x[3*n], xn1 = x[3*n+1], xn2 = x[3*n+2];
        float vn2 = fmaf(xn0, xn0, fmaf(xn1, xn1, xn2 * xn2));
        float v = sqrtf(vn2);
        float d2 = um2 + vn2 - 2.f * fmaf(xm0, xn0, fmaf(xm1, xn1, xm2 * xn2));
        float d = sqrtf(fmaxf(d2, 0.f));
        float v2 = v * v, v3 = v2 * v, v4 = v2 * v2;
        float dd2 = d * d, dd3 = dd2 * d, dd4 = dd2 * dd2;
        const int pr = t >> 1, ln = t & 1;
        smP[pr][0][ln]  = v;      smP[pr][1][ln]  = v2;
        smP[pr][2][ln]  = v3;     smP[pr][3][ln]  = v4;
        smP[pr][4][ln]  = d;      smP[pr][5][ln]  = d*v;
        smP[pr][6][ln]  = d*v2;   smP[pr][7][ln]  = d*v3;
        smP[pr][8][ln]  = dd2;    smP[pr][9][ln]  = dd2*v;
        smP[pr][10][ln] = dd2*v2; smP[pr][11][ln] = dd3;
        smP[pr][12][ln] = dd3*v;  smP[pr][13][ln] = dd4;
        smX[0][t] = xn0; smX[1][t] = xn1; smX[2][t] = xn2;
        __syncthreads();
    }

    float M0 = -1e30f, M1 = -1e30f;
    ull D2 = pack2(0.f, 0.f);
    ull A0 = D2, A1 = D2, A2 = D2;

    for (int tile = 0; tile < NTILES; ++tile) {
        // ---- phase 2: packed poly eval + branchless exact online softmax ----
        #pragma unroll 2
        for (int nn = 0; nn < TILE / 2; ++nn) {
            ull la = paf2[0], lb = pbf2[0];
            #pragma unroll
            for (int sj = 0; sj < 14; sj += 2) {
                ulonglong2 q = *(const ulonglong2*)&smP[nn][sj][0];
                la = ffma2(paf2[sj + 1], q.x, la);
                lb = ffma2(pbf2[sj + 1], q.x, lb);
                la = ffma2(paf2[sj + 2], q.y, la);
                lb = ffma2(pbf2[sj + 2], q.y, lb);
            }
            ull h2 = fmul2(la, lb);          // log2 units
            float h0, h1;
            unpack2(h0, h1, h2);

            float dd0 = h0 - M0, dd1 = h1 - M1;
            float q0 = ex2(-fabsf(dd0)), q1 = ex2(-fabsf(dd1));
            bool g0 = dd0 > 0.f, g1 = dd1 > 0.f;
            float r0 = g0 ? q0 : 1.f, e0 = g0 ? 1.f : q0;
            float r1 = g1 ? q1 : 1.f, e1 = g1 ? 1.f : q1;
            M0 = fmaxf(M0, h0);
            M1 = fmaxf(M1, h1);
            ull r2 = pack2(r0, r1), e2 = pack2(e0, e1);
            D2 = ffma2(D2, r2, e2);
            A0 = ffma2(A0, r2, fmul2(e2, *(const ull*)&smX[0][2*nn]));
            A1 = ffma2(A1, r2, fmul2(e2, *(const ull*)&smX[1][2*nn]));
            A2 = ffma2(A2, r2, fmul2(e2, *(const ull*)&smX[2][2*nn]));
        }

        // ---- phase 1 for next tile ----
        if (tile + 1 < NTILES) {
            const int n = (tile + 1) * TILE + t;
            float xn0 = x[3*n], xn1 = x[3*n+1], xn2 = x[3*n+2];
            float vn2 = fmaf(xn0, xn0, fmaf(xn1, xn1, xn2 * xn2));
            float v = sqrtf(vn2);
            float d2 = um2 + vn2 - 2.f * fmaf(xm0, xn0, fmaf(xm1, xn1, xm2 * xn2));
            float d = sqrtf(fmaxf(d2, 0.f));
            float v2 = v * v, v3 = v2 * v, v4 = v2 * v2;
            float dd2 = d * d, dd3 = dd2 * d, dd4 = dd2 * dd2;
            __syncthreads();     // this tile's readers are done
            const int pr = t >> 1, ln = t & 1;
            smP[pr][0][ln]  = v;      smP[pr][1][ln]  = v2;
            smP[pr][2][ln]  = v3;     smP[pr][3][ln]  = v4;
            smP[pr][4][ln]  = d;      smP[pr][5][ln]  = d*v;
            smP[pr][6][ln]  = d*v2;   smP[pr][7][ln]  = d*v3;
            smP[pr][8][ln]  = dd2;    smP[pr][9][ln]  = dd2*v;
            smP[pr][10][ln] = dd2*v2; smP[pr][11][ln] = dd3;
            smP[pr][12][ln] = dd3*v;  smP[pr][13][ln] = dd4;
            smX[0][t] = xn0; smX[1][t] = xn1; smX[2][t] = xn2;
            __syncthreads();
        }
    }

    // ---- epilogue: merge even/odd lanes (different M), normalize, write ----
    float D0, D1, a00, a10, a01, a11, a02, a12;
    unpack2(D0, D1, D2);
    unpack2(a00, a10, A0);
    unpack2(a01, a11, A1);
    unpack2(a02, a12, A2);
    float Mm = fmaxf(M0, M1);
    float r0 = ex2(M0 - Mm);
    float r1 = ex2(M1 - Mm);
    float inv = 1.f / fmaf(D0, r0, D1 * r1);
    g_norm[0][m][t] = fmaf(a00, r0, a10 * r1) * inv;
    g_norm[1][m][t] = fmaf(a01, r0, a11 * r1) * inv;
    g_norm[2][m][t] = fmaf(a02, r0, a12 * r1) * inv;
}

// ---------------------------------------------------------------------------
// Reduce: single CTA, 1024 threads (8 m-slices x 128 channels). Sums g_norm
// over m, applies Wf, tree-reduces over channels, emits the 9 output floats.
// Deterministic fixed-order reduction.
// ---------------------------------------------------------------------------
__global__ void __launch_bounds__(1024) reduce_kernel(const float* __restrict__ x,
                                                      const float* __restrict__ Wf,
                                                      float* __restrict__ out)
{
    __shared__ float sh[3][8][CC];
    __shared__ float red[6][CC];
    const int c = threadIdx.x & 127;
    const int sl = threadIdx.x >> 7;          // 0..7
    const int m0 = sl * (NP / 8);              // 96 m per slice
    float s0 = 0.f, s1 = 0.f, s2 = 0.f;
    #pragma unroll 4
    for (int mi = 0; mi < NP / 8; ++mi) {
        s0 += g_norm[0][m0 + mi][c];
        s1 += g_norm[1][m0 + mi][c];
        s2 += g_norm[2][m0 + mi][c];
    }
    sh[0][sl][c] = s0; sh[1][sl][c] = s1; sh[2][sl][c] = s2;
    __syncthreads();
    for (int off = 4; off > 0; off >>= 1) {
        if (sl < off) {
            #pragma unroll
            for (int q = 0; q < 3; ++q)
                sh[q][sl][c] += sh[q][sl + off][c];
        }
        __syncthreads();
    }
    if (sl == 0) {
        float w0 = Wf[c], w1 = Wf[CC + c];
        float t0 = sh[0][0][c], t1 = sh[1][0][c], t2 = sh[2][0][c];
        red[0][c] = w0 * t0; red[1][c] = w0 * t1; red[2][c] = w0 * t2;
        red[3][c] = w1 * t0; red[4][c] = w1 * t1; red[5][c] = w1 * t2;
    }
    __syncthreads();
    for (int off = 64; off > 0; off >>= 1) {
        if (sl == 0 && c < off) {
            #pragma unroll
            for (int q = 0; q < 6; ++q) red[q][c] += red[q][c + off];
        }
        __syncthreads();
    }
    if (threadIdx.x < 3) out[threadIdx.x] = x[threadIdx.x];   // row 0 = x[0,0,:]
    if (threadIdx.x == 0) {
        #pragma unroll
        for (int q = 0; q < 6; ++q) out[3 + q] = red[q][0];
    }
}

extern "C" void kernel_launch(void* const* d_in, const int* in_sizes, int n_in,
                              void* d_out, int out_size)
{
    const float* x   = (const float*)d_in[0];
    const float* Wa1 = (const float*)d_in[1];
    const float* ba1 = (const float*)d_in[2];
    const float* Wb1 = (const float*)d_in[3];
    const float* bb1 = (const float*)d_in[4];
    const float* Wa2 = (const float*)d_in[5];
    const float* ba2 = (const float*)d_in[6];
    const float* Wb2 = (const float*)d_in[7];
    const float* bb2 = (const float*)d_in[8];
    const float* Wa3 = (const float*)d_in[9];
    const float* ba3 = (const float*)d_in[10];
    const float* Wb3 = (const float*)d_in[11];
    const float* bb3 = (const float*)d_in[12];
    const float* Wf  = (const float*)d_in[13];

    precompute_kernel<<<1, 512>>>(Wa1, ba1, Wb1, bb1,
                                  Wa2, ba2, Wb2, bb2,
                                  Wa3, ba3, Wb3, bb3);
    fps_main_kernel<<<NP, 128>>>(x);
    reduce_kernel<<<1, 1024>>>(x, Wf, (float*)d_out);
}

// round 15
// speedup vs baseline: 1.8586x; 1.8586x over previous
#include <cuda_runtime.h>

#define NP 768
#define CC 128
#define TILE 128
#define NTILES (NP / TILE)    // 6 n-tiles per CTA
#define L2E 1.4426950408889634f

// Quartic polynomial coefficients: [o][monomial j][channel]
__device__ float g_P[2][35][CC];
// Layer-2 expansion, transposed: [monomial j][channel]
__device__ float g_Et[35][CC];
// Normalized per-(m,c) softmax aggregates: [q in 0..2][m][c]
__device__ float g_norm[3][NP][CC];

// ---------------- f32x2 packed helpers (sm_103a) ----------------
typedef unsigned long long ull;
__device__ __forceinline__ ull pack2(float lo, float hi) {
    ull r;
    asm("mov.b64 %0, {%1,%2};" : "=l"(r) : "f"(lo), "f"(hi));
    return r;
}
__device__ __forceinline__ void unpack2(float& lo, float& hi, ull v) {
    asm("mov.b64 {%0,%1}, %2;" : "=f"(lo), "=f"(hi) : "l"(v));
}
__device__ __forceinline__ ull ffma2(ull a, ull b, ull c) {
    ull d;
    asm("fma.rn.f32x2 %0, %1, %2, %3;" : "=l"(d) : "l"(a), "l"(b), "l"(c));
    return d;
}
__device__ __forceinline__ ull fmul2(ull a, ull b) {
    ull d;
    asm("mul.rn.f32x2 %0, %1, %2;" : "=l"(d) : "l"(a), "l"(b));
    return d;
}
// bare hardware exp2 (no libdevice fixups)
__device__ __forceinline__ float ex2(float x) {
    float y;
    asm("ex2.approx.ftz.f32 %0, %1;" : "=f"(y) : "f"(x));
    return y;
}

// ---------------------------------------------------------------------------
// P1: layers 1+2 + quartic expansion. One CTA, 128 threads (thread=channel).
// W2 rows loaded directly per-thread via LDG.128 (32 independent loads ->
// single latency exposure). Expansion goes through SHARED memory (dynamic
// LUT indexing is spill-free there). Output g_Et[j][c], coalesced stores.
// Monomials (35): a=0..4 (d), b=0..4-a (u), c=0..4-a-b (v), lexicographic.
// ---------------------------------------------------------------------------
__global__ void __launch_bounds__(128) precompA_kernel(
    const float* __restrict__ Wa1, const float* __restrict__ ba1,
    const float* __restrict__ Wb1, const float* __restrict__ bb1,
    const float* __restrict__ Wa2, const float* __restrict__ ba2,
    const float* __restrict__ Wb2, const float* __restrict__ bb2)
{
    __shared__ float sV[CC][10];
    __shared__ float sE[CC][35];
    __shared__ int sLUT[125];
    const int t = threadIdx.x;

    if (t == 0) {
        int j = 0;
        for (int a = 0; a <= 4; ++a)
            for (int b = 0; b <= 4 - a; ++b)
                for (int cc = 0; cc <= 4 - a - b; ++cc)
                    sLUT[a * 25 + b * 5 + cc] = j++;
    }
    // Layer 1: homogeneous vectors over g = (d,u,v,1) -> pairwise products
    {
        float A0 = Wa1[3*t], A1 = Wa1[3*t+1], A2 = Wa1[3*t+2], A3 = ba1[t];
        float B0 = Wb1[3*t], B1 = Wb1[3*t+1], B2 = Wb1[3*t+2], B3 = bb1[t];
        sV[t][0] = A0*B0;
        sV[t][1] = A0*B1 + A1*B0;
        sV[t][2] = A0*B2 + A2*B0;
        sV[t][3] = A0*B3 + A3*B0;
        sV[t][4] = A1*B1;
        sV[t][5] = A1*B2 + A2*B1;
        sV[t][6] = A1*B3 + A3*B1;
        sV[t][7] = A2*B2;
        sV[t][8] = A2*B3 + A3*B2;
        sV[t][9] = A3*B3;
    }
    __syncthreads();

    // Layer 2: quadratic forms qa/qb via direct LDG.128 of this channel's rows
    float qa[10], qb[10];
    #pragma unroll
    for (int p = 0; p < 10; ++p) { qa[p] = 0.f; qb[p] = 0.f; }
    {
        const float4* wa4 = (const float4*)(Wa2 + t * CC);
        const float4* wb4 = (const float4*)(Wb2 + t * CC);
        #pragma unroll 8
        for (int q4 = 0; q4 < 32; ++q4) {
            float4 wa = __ldg(wa4 + q4);
            float4 wb = __ldg(wb4 + q4);
            int kb = q4 * 4;
            float was[4] = {wa.x, wa.y, wa.z, wa.w};
            float wbs[4] = {wb.x, wb.y, wb.z, wb.w};
            #pragma unroll
            for (int kk = 0; kk < 4; ++kk) {
                const float* vv = &sV[kb + kk][0];
                #pragma unroll
                for (int p = 0; p < 10; ++p) {
                    qa[p] = fmaf(was[kk], vv[p], qa[p]);
                    qb[p] = fmaf(wbs[kk], vv[p], qb[p]);
                }
            }
        }
    }
    qa[9] += ba2[t];                     // bias = constant monomial
    qb[9] += bb2[t];

    // Expansion: h2 = Qa*Qb -> quartic (35 coefficients), through shared mem
    #pragma unroll
    for (int j = 0; j < 35; ++j) sE[t][j] = 0.f;
    {
        const int pk[10] = {50, 30, 26, 25, 10, 6, 5, 2, 1, 0};
        #pragma unroll
        for (int p = 0; p < 10; ++p) {
            float va = qa[p];
            #pragma unroll
            for (int q = 0; q < 10; ++q)
                sE[t][sLUT[pk[p] + pk[q]]] += va * qb[q];
        }
    }
    __syncthreads();

    // Write transposed: g_Et[j][c]; coalesced across threads for each j
    #pragma unroll
    for (int j = 0; j < 35; ++j)
        g_Et[j][t] = sE[t][j];
}

// ---------------------------------------------------------------------------
// P2: layer 3 in parallel. Grid = 35 CTAs (one per monomial j), 256 threads:
// o = t>>7 selects Wa3/Wb3, c = t&127 the output channel.
// g_P[o][j][c] = sum_k W3[o][c][k] * E[k][j]  (+ bias on j==0)
// ---------------------------------------------------------------------------
__global__ void __launch_bounds__(256) precompB_kernel(
    const float* __restrict__ Wa3, const float* __restrict__ ba3,
    const float* __restrict__ Wb3, const float* __restrict__ bb3)
{
    __shared__ float sEj[CC];
    const int j = blockIdx.x;
    const int t = threadIdx.x;
    const int c = t & 127;
    const int o = t >> 7;

    if (t < CC) sEj[t] = g_Et[j][t];     // coalesced
    __syncthreads();

    const float* W = o ? Wb3 : Wa3;
    const float4* w4 = (const float4*)(W + c * CC);
    float acc = 0.f;
    #pragma unroll 8
    for (int q4 = 0; q4 < 32; ++q4) {
        float4 w = __ldg(w4 + q4);
        const float* e = &sEj[q4 * 4];
        acc = fmaf(w.x, e[0], acc);
        acc = fmaf(w.y, e[1], acc);
        acc = fmaf(w.z, e[2], acc);
        acc = fmaf(w.w, e[3], acc);
    }
    if (j == 0) acc += o ? bb3[c] : ba3[c];   // bias on constant monomial
    g_P[o][j][c] = acc;
}

// ---------------------------------------------------------------------------
// Main: one CTA per m. Thread = channel. Branchless ALWAYS-RESCALE online
// softmax (exact): with d = h - M, q = ex2(-|d|), exactly one of {rescale r,
// new term e} equals q and the other equals 1. All ex2 args <= 0 -> no
// overflow; D >= 1 after the first step -> no 0/0.
// ---------------------------------------------------------------------------
__global__ void __launch_bounds__(128, 5) fps_main_kernel(const float* __restrict__ x)
{
    // interleaved monomials: [pair nn][slot 0..13, pad to 18][even/odd]
    __shared__ __align__(16) float smP[TILE/2][18][2];
    __shared__ __align__(16) float smX[3][TILE];
    const int m = blockIdx.x;
    const int t = threadIdx.x;

    const float xm0 = x[3*m], xm1 = x[3*m+1], xm2 = x[3*m+2];
    const float um2 = fmaf(xm0, xm0, fmaf(xm1, xm1, xm2 * xm2));
    const float u = sqrtf(um2);

    // ---- prologue: fold u^b into coefficients, pack duplicated f32x2 ----
    float up[5];
    up[0] = 1.f; up[1] = u; up[2] = um2; up[3] = um2 * u; up[4] = um2 * um2;
    const int JB[35] = {0,0,0,0,0, 1,1,1,1, 2,2,2, 3,3, 4,
                        0,0,0,0, 1,1,1, 2,2, 3,
                        0,0,0, 1,1, 2,
                        0,0, 1, 0};
    const int JF[35] = {0,1,2,3,4, 0,1,2,3, 0,1,2, 0,1, 0,
                        5,6,7,8, 5,6,7, 5,6, 5,
                        9,10,11, 9,10, 9,
                        12,13, 12, 14};
    float paf[15], pbf[15];
    #pragma unroll
    for (int f = 0; f < 15; ++f) { paf[f] = 0.f; pbf[f] = 0.f; }
    #pragma unroll
    for (int j = 0; j < 35; ++j) {
        float ub = up[JB[j]];
        paf[JF[j]] = fmaf(g_P[0][j][t], ub, paf[JF[j]]);
        pbf[JF[j]] = fmaf(g_P[1][j][t], ub, pbf[JF[j]]);
    }
    ull paf2[15], pbf2[15];
    #pragma unroll
    for (int j = 0; j < 15; ++j) {
        float a = paf[j] * L2E;              // fold log2(e) into P_a
        paf2[j] = pack2(a, a);
        pbf2[j] = pack2(pbf[j], pbf[j]);
    }

    // ---- phase 1 for tile 0 ----
    {
        const int n = t;
        float xn0 = x[3*n], xn1 = x[3*n+1], xn2 = x[3*n+2];
        float vn2 = fmaf(xn0, xn0, fmaf(xn1, xn1, xn2 * xn2));
        float v = sqrtf(vn2);
        float d2 = um2 + vn2 - 2.f * fmaf(xm0, xn0, fmaf(xm1, xn1, xm2 * xn2));
        float d = sqrtf(fmaxf(d2, 0.f));
        float v2 = v * v, v3 = v2 * v, v4 = v2 * v2;
        float dd2 = d * d, dd3 = dd2 * d, dd4 = dd2 * dd2;
        const int pr = t >> 1, ln = t & 1;
        smP[pr][0][ln]  = v;      smP[pr][1][ln]  = v2;
        smP[pr][2][ln]  = v3;     smP[pr][3][ln]  = v4;
        smP[pr][4][ln]  = d;      smP[pr][5][ln]  = d*v;
        smP[pr][6][ln]  = d*v2;   smP[pr][7][ln]  = d*v3;
        smP[pr][8][ln]  = dd2;    smP[pr][9][ln]  = dd2*v;
        smP[pr][10][ln] = dd2*v2; smP[pr][11][ln] = dd3;
        smP[pr][12][ln] = dd3*v;  smP[pr][13][ln] = dd4;
        smX[0][t] = xn0; smX[1][t] = xn1; smX[2][t] = xn2;
        __syncthreads();
    }

    float M0 = -1e30f, M1 = -1e30f;
    ull D2 = pack2(0.f, 0.f);
    ull A0 = D2, A1 = D2, A2 = D2;

    for (int tile = 0; tile < NTILES; ++tile) {
        // ---- phase 2: packed poly eval + branchless exact online softmax ----
        #pragma unroll 2
        for (int nn = 0; nn < TILE / 2; ++nn) {
            ull la = paf2[0], lb = pbf2[0];
            #pragma unroll
            for (int sj = 0; sj < 14; sj += 2) {
                ulonglong2 q = *(const ulonglong2*)&smP[nn][sj][0];
                la = ffma2(paf2[sj + 1], q.x, la);
                lb = ffma2(pbf2[sj + 1], q.x, lb);
                la = ffma2(paf2[sj + 2], q.y, la);
                lb = ffma2(pbf2[sj + 2], q.y, lb);
            }
            ull h2 = fmul2(la, lb);          // log2 units
            float h0, h1;
            unpack2(h0, h1, h2);

            float dd0 = h0 - M0, dd1 = h1 - M1;
            float q0 = ex2(-fabsf(dd0)), q1 = ex2(-fabsf(dd1));
            bool g0 = dd0 > 0.f, g1 = dd1 > 0.f;
            float r0 = g0 ? q0 : 1.f, e0 = g0 ? 1.f : q0;
            float r1 = g1 ? q1 : 1.f, e1 = g1 ? 1.f : q1;
            M0 = fmaxf(M0, h0);
            M1 = fmaxf(M1, h1);
            ull r2 = pack2(r0, r1), e2 = pack2(e0, e1);
            D2 = ffma2(D2, r2, e2);
            A0 = ffma2(A0, r2, fmul2(e2, *(const ull*)&smX[0][2*nn]));
            A1 = ffma2(A1, r2, fmul2(e2, *(const ull*)&smX[1][2*nn]));
            A2 = ffma2(A2, r2, fmul2(e2, *(const ull*)&smX[2][2*nn]));
        }

        // ---- phase 1 for next tile ----
        if (tile + 1 < NTILES) {
            const int n = (tile + 1) * TILE + t;
            float xn0 = x[3*n], xn1 = x[3*n+1], xn2 = x[3*n+2];
            float vn2 = fmaf(xn0, xn0, fmaf(xn1, xn1, xn2 * xn2));
            float v = sqrtf(vn2);
            float d2 = um2 + vn2 - 2.f * fmaf(xm0, xn0, fmaf(xm1, xn1, xm2 * xn2));
            float d = sqrtf(fmaxf(d2, 0.f));
            float v2 = v * v, v3 = v2 * v, v4 = v2 * v2;
            float dd2 = d * d, dd3 = dd2 * d, dd4 = dd2 * dd2;
            __syncthreads();     // this tile's readers are done
            const int pr = t >> 1, ln = t & 1;
            smP[pr][0][ln]  = v;      smP[pr][1][ln]  = v2;
            smP[pr][2][ln]  = v3;     smP[pr][3][ln]  = v4;
            smP[pr][4][ln]  = d;      smP[pr][5][ln]  = d*v;
            smP[pr][6][ln]  = d*v2;   smP[pr][7][ln]  = d*v3;
            smP[pr][8][ln]  = dd2;    smP[pr][9][ln]  = dd2*v;
            smP[pr][10][ln] = dd2*v2; smP[pr][11][ln] = dd3;
            smP[pr][12][ln] = dd3*v;  smP[pr][13][ln] = dd4;
            smX[0][t] = xn0; smX[1][t] = xn1; smX[2][t] = xn2;
            __syncthreads();
        }
    }

    // ---- epilogue: merge even/odd lanes (different M), normalize, write ----
    float D0, D1, a00, a10, a01, a11, a02, a12;
    unpack2(D0, D1, D2);
    unpack2(a00, a10, A0);
    unpack2(a01, a11, A1);
    unpack2(a02, a12, A2);
    float Mm = fmaxf(M0, M1);
    float r0 = ex2(M0 - Mm);
    float r1 = ex2(M1 - Mm);
    float inv = 1.f / fmaf(D0, r0, D1 * r1);
    g_norm[0][m][t] = fmaf(a00, r0, a10 * r1) * inv;
    g_norm[1][m][t] = fmaf(a01, r0, a11 * r1) * inv;
    g_norm[2][m][t] = fmaf(a02, r0, a12 * r1) * inv;
}

// ---------------------------------------------------------------------------
// Reduce: single CTA, 1024 threads (8 m-slices x 128 channels). Sums g_norm
// over m, applies Wf, tree-reduces over channels, emits the 9 output floats.
// Deterministic fixed-order reduction.
// ---------------------------------------------------------------------------
__global__ void __launch_bounds__(1024) reduce_kernel(const float* __restrict__ x,
                                                      const float* __restrict__ Wf,
                                                      float* __restrict__ out)
{
    __shared__ float sh[3][8][CC];
    __shared__ float red[6][CC];
    const int c = threadIdx.x & 127;
    const int sl = threadIdx.x >> 7;          // 0..7
    const int m0 = sl * (NP / 8);              // 96 m per slice
    float s0 = 0.f, s1 = 0.f, s2 = 0.f;
    #pragma unroll 4
    for (int mi = 0; mi < NP / 8; ++mi) {
        s0 += g_norm[0][m0 + mi][c];
        s1 += g_norm[1][m0 + mi][c];
        s2 += g_norm[2][m0 + mi][c];
    }
    sh[0][sl][c] = s0; sh[1][sl][c] = s1; sh[2][sl][c] = s2;
    __syncthreads();
    for (int off = 4; off > 0; off >>= 1) {
        if (sl < off) {
            #pragma unroll
            for (int q = 0; q < 3; ++q)
                sh[q][sl][c] += sh[q][sl + off][c];
        }
        __syncthreads();
    }
    if (sl == 0) {
        float w0 = Wf[c], w1 = Wf[CC + c];
        float t0 = sh[0][0][c], t1 = sh[1][0][c], t2 = sh[2][0][c];
        red[0][c] = w0 * t0; red[1][c] = w0 * t1; red[2][c] = w0 * t2;
        red[3][c] = w1 * t0; red[4][c] = w1 * t1; red[5][c] = w1 * t2;
    }
    __syncthreads();
    for (int off = 64; off > 0; off >>= 1) {
        if (sl == 0 && c < off) {
            #pragma unroll
            for (int q = 0; q < 6; ++q) red[q][c] += red[q][c + off];
        }
        __syncthreads();
    }
    if (threadIdx.x < 3) out[threadIdx.x] = x[threadIdx.x];   // row 0 = x[0,0,:]
    if (threadIdx.x == 0) {
        #pragma unroll
        for (int q = 0; q < 6; ++q) out[3 + q] = red[q][0];
    }
}

extern "C" void kernel_launch(void* const* d_in, const int* in_sizes, int n_in,
                              void* d_out, int out_size)
{
    const float* x   = (const float*)d_in[0];
    const float* Wa1 = (const float*)d_in[1];
    const float* ba1 = (const float*)d_in[2];
    const float* Wb1 = (const float*)d_in[3];
    const float* bb1 = (const float*)d_in[4];
    const float* Wa2 = (const float*)d_in[5];
    const float* ba2 = (const float*)d_in[6];
    const float* Wb2 = (const float*)d_in[7];
    const float* bb2 = (const float*)d_in[8];
    const float* Wa3 = (const float*)d_in[9];
    const float* ba3 = (const float*)d_in[10];
    const float* Wb3 = (const float*)d_in[11];
    const float* bb3 = (const float*)d_in[12];
    const float* Wf  = (const float*)d_in[13];

    precompA_kernel<<<1, 128>>>(Wa1, ba1, Wb1, bb1, Wa2, ba2, Wb2, bb2);
    precompB_kernel<<<35, 256>>>(Wa3, ba3, Wb3, bb3);
    fps_main_kernel<<<NP, 128>>>(x);
    reduce_kernel<<<1, 1024>>>(x, Wf, (float*)d_out);
}

// round 17
// speedup vs baseline: 1.9085x; 1.0268x over previous
#include <cuda_runtime.h>

#define NP 768
#define CC 128
#define TILE 128
#define NSPLIT 2
#define TPC 3                 // tiles per CTA (NSPLIT*TPC*TILE == NP)
#define L2E 1.4426950408889634f
#define RBLK 48               // reduceA blocks (16 m each)

// Quartic polynomial coefficients: [o][monomial j][channel]
__device__ float g_P[2][35][CC];
// Layer-2 expansion, transposed: [monomial j][channel]
__device__ float g_Et[35][CC];
// Partial softmax stats per (m, split): {M(log2), D, A0, A1, A2} x channel
__device__ float g_part[NP][NSPLIT][5][CC];
// Stage-A partial sums: [q in 0..2][blk][c]
__device__ float g_red[3][RBLK][CC];

// ---------------- f32x2 packed helpers (sm_103a) ----------------
typedef unsigned long long ull;
__device__ __forceinline__ ull pack2(float lo, float hi) {
    ull r;
    asm("mov.b64 %0, {%1,%2};" : "=l"(r) : "f"(lo), "f"(hi));
    return r;
}
__device__ __forceinline__ void unpack2(float& lo, float& hi, ull v) {
    asm("mov.b64 {%0,%1}, %2;" : "=f"(lo), "=f"(hi) : "l"(v));
}
__device__ __forceinline__ ull ffma2(ull a, ull b, ull c) {
    ull d;
    asm("fma.rn.f32x2 %0, %1, %2, %3;" : "=l"(d) : "l"(a), "l"(b), "l"(c));
    return d;
}
__device__ __forceinline__ ull fmul2(ull a, ull b) {
    ull d;
    asm("mul.rn.f32x2 %0, %1, %2;" : "=l"(d) : "l"(a), "l"(b));
    return d;
}
// bare hardware exp2 (no libdevice fixups)
__device__ __forceinline__ float ex2(float x) {
    float y;
    asm("ex2.approx.ftz.f32 %0, %1;" : "=f"(y) : "f"(x));
    return y;
}

// ---------------------------------------------------------------------------
// P1: layers 1+2 + quartic expansion. One CTA, 128 threads (thread=channel).
// ---------------------------------------------------------------------------
__global__ void __launch_bounds__(128) precompA_kernel(
    const float* __restrict__ Wa1, const float* __restrict__ ba1,
    const float* __restrict__ Wb1, const float* __restrict__ bb1,
    const float* __restrict__ Wa2, const float* __restrict__ ba2,
    const float* __restrict__ Wb2, const float* __restrict__ bb2)
{
    __shared__ float sV[CC][10];
    __shared__ float sE[CC][35];
    __shared__ int sLUT[125];
    const int t = threadIdx.x;

    if (t == 0) {
        int j = 0;
        for (int a = 0; a <= 4; ++a)
            for (int b = 0; b <= 4 - a; ++b)
                for (int cc = 0; cc <= 4 - a - b; ++cc)
                    sLUT[a * 25 + b * 5 + cc] = j++;
    }
    {
        float A0 = Wa1[3*t], A1 = Wa1[3*t+1], A2 = Wa1[3*t+2], A3 = ba1[t];
        float B0 = Wb1[3*t], B1 = Wb1[3*t+1], B2 = Wb1[3*t+2], B3 = bb1[t];
        sV[t][0] = A0*B0;
        sV[t][1] = A0*B1 + A1*B0;
        sV[t][2] = A0*B2 + A2*B0;
        sV[t][3] = A0*B3 + A3*B0;
        sV[t][4] = A1*B1;
        sV[t][5] = A1*B2 + A2*B1;
        sV[t][6] = A1*B3 + A3*B1;
        sV[t][7] = A2*B2;
        sV[t][8] = A2*B3 + A3*B2;
        sV[t][9] = A3*B3;
    }
    __syncthreads();

    float qa[10], qb[10];
    #pragma unroll
    for (int p = 0; p < 10; ++p) { qa[p] = 0.f; qb[p] = 0.f; }
    {
        const float4* wa4 = (const float4*)(Wa2 + t * CC);
        const float4* wb4 = (const float4*)(Wb2 + t * CC);
        #pragma unroll 8
        for (int q4 = 0; q4 < 32; ++q4) {
            float4 wa = __ldg(wa4 + q4);
            float4 wb = __ldg(wb4 + q4);
            int kb = q4 * 4;
            float was[4] = {wa.x, wa.y, wa.z, wa.w};
            float wbs[4] = {wb.x, wb.y, wb.z, wb.w};
            #pragma unroll
            for (int kk = 0; kk < 4; ++kk) {
                const float* vv = &sV[kb + kk][0];
                #pragma unroll
                for (int p = 0; p < 10; ++p) {
                    qa[p] = fmaf(was[kk], vv[p], qa[p]);
                    qb[p] = fmaf(wbs[kk], vv[p], qb[p]);
                }
            }
        }
    }
    qa[9] += ba2[t];
    qb[9] += bb2[t];

    #pragma unroll
    for (int j = 0; j < 35; ++j) sE[t][j] = 0.f;
    {
        const int pk[10] = {50, 30, 26, 25, 10, 6, 5, 2, 1, 0};
        #pragma unroll
        for (int p = 0; p < 10; ++p) {
            float va = qa[p];
            #pragma unroll
            for (int q = 0; q < 10; ++q)
                sE[t][sLUT[pk[p] + pk[q]]] += va * qb[q];
        }
    }
    __syncthreads();

    #pragma unroll
    for (int j = 0; j < 35; ++j)
        g_Et[j][t] = sE[t][j];
}

// ---------------------------------------------------------------------------
// P2: layer 3 in parallel. Grid = 35 CTAs (one per monomial j), 256 threads.
// ---------------------------------------------------------------------------
__global__ void __launch_bounds__(256) precompB_kernel(
    const float* __restrict__ Wa3, const float* __restrict__ ba3,
    const float* __restrict__ Wb3, const float* __restrict__ bb3)
{
    __shared__ float sEj[CC];
    const int j = blockIdx.x;
    const int t = threadIdx.x;
    const int c = t & 127;
    const int o = t >> 7;

    if (t < CC) sEj[t] = g_Et[j][t];
    __syncthreads();

    const float* W = o ? Wb3 : Wa3;
    const float4* w4 = (const float4*)(W + c * CC);
    float acc = 0.f;
    #pragma unroll 8
    for (int q4 = 0; q4 < 32; ++q4) {
        float4 w = __ldg(w4 + q4);
        const float* e = &sEj[q4 * 4];
        acc = fmaf(w.x, e[0], acc);
        acc = fmaf(w.y, e[1], acc);
        acc = fmaf(w.z, e[2], acc);
        acc = fmaf(w.w, e[3], acc);
    }
    if (j == 0) acc += o ? bb3[c] : ba3[c];
    g_P[o][j][c] = acc;
}

// ---------------------------------------------------------------------------
// Main: one CTA per (m, n-split of 384). 3 internal tiles. Thread = channel.
// Branchless ALWAYS-RESCALE online softmax (exact). Writes raw per-split
// stats {M(log2), D, A0..2} to g_part.
// ---------------------------------------------------------------------------
__global__ void __launch_bounds__(128, 5) fps_main_kernel(const float* __restrict__ x)
{
    __shared__ __align__(16) float smP[TILE/2][18][2];
    __shared__ __align__(16) float smX[3][TILE];
    const int m = blockIdx.x;
    const int s = blockIdx.y;
    const int t = threadIdx.x;

    const float xm0 = x[3*m], xm1 = x[3*m+1], xm2 = x[3*m+2];
    const float um2 = fmaf(xm0, xm0, fmaf(xm1, xm1, xm2 * xm2));
    const float u = sqrtf(um2);

    // ---- prologue: fold u^b into coefficients, pack duplicated f32x2 ----
    float up[5];
    up[0] = 1.f; up[1] = u; up[2] = um2; up[3] = um2 * u; up[4] = um2 * um2;
    const int JB[35] = {0,0,0,0,0, 1,1,1,1, 2,2,2, 3,3, 4,
                        0,0,0,0, 1,1,1, 2,2, 3,
                        0,0,0, 1,1, 2,
                        0,0, 1, 0};
    const int JF[35] = {0,1,2,3,4, 0,1,2,3, 0,1,2, 0,1, 0,
                        5,6,7,8, 5,6,7, 5,6, 5,
                        9,10,11, 9,10, 9,
                        12,13, 12, 14};
    float paf[15], pbf[15];
    #pragma unroll
    for (int f = 0; f < 15; ++f) { paf[f] = 0.f; pbf[f] = 0.f; }
    #pragma unroll
    for (int j = 0; j < 35; ++j) {
        float ub = up[JB[j]];
        paf[JF[j]] = fmaf(g_P[0][j][t], ub, paf[JF[j]]);
        pbf[JF[j]] = fmaf(g_P[1][j][t], ub, pbf[JF[j]]);
    }
    ull paf2[15], pbf2[15];
    #pragma unroll
    for (int j = 0; j < 15; ++j) {
        float a = paf[j] * L2E;              // fold log2(e) into P_a
        paf2[j] = pack2(a, a);
        pbf2[j] = pack2(pbf[j], pbf[j]);
    }

    // ---- phase 1 for tile 0 of this split ----
    {
        const int n = s * (TPC * TILE) + t;
        float xn0 = x[3*n], xn1 = x[3*n+1], xn2 = x[3*n+2];
        float vn2 = fmaf(xn0, xn0, fmaf(xn1, xn1, xn2 * xn2));
        float v = sqrtf(vn2);
        float d2 = um2 + vn2 - 2.f * fmaf(xm0, xn0, fmaf(xm1, xn1, xm2 * xn2));
        float d = sqrtf(fmaxf(d2, 0.f));
        float v2 = v * v, v3 = v2 * v, v4 = v2 * v2;
        float dd2 = d * d, dd3 = dd2 * d, dd4 = dd2 * dd2;
        const int pr = t >> 1, ln = t & 1;
        smP[pr][0][ln]  = v;      smP[pr][1][ln]  = v2;
        smP[pr][2][ln]  = v3;     smP[pr][3][ln]  = v4;
        smP[pr][4][ln]  = d;      smP[pr][5][ln]  = d*v;
        smP[pr][6][ln]  = d*v2;   smP[pr][7][ln]  = d*v3;
        smP[pr][8][ln]  = dd2;    smP[pr][9][ln]  = dd2*v;
        smP[pr][10][ln] = dd2*v2; smP[pr][11][ln] = dd3;
        smP[pr][12][ln] = dd3*v;  smP[pr][13][ln] = dd4;
        smX[0][t] = xn0; smX[1][t] = xn1; smX[2][t] = xn2;
        __syncthreads();
    }

    float M0 = -1e30f, M1 = -1e30f;
    ull D2 = pack2(0.f, 0.f);
    ull A0 = D2, A1 = D2, A2 = D2;

    for (int tile = 0; tile < TPC; ++tile) {
        // ---- phase 2: packed poly eval + branchless exact online softmax ----
        #pragma unroll 2
        for (int nn = 0; nn < TILE / 2; ++nn) {
            ull la = paf2[0], lb = pbf2[0];
            #pragma unroll
            for (int sj = 0; sj < 14; sj += 2) {
                ulonglong2 q = *(const ulonglong2*)&smP[nn][sj][0];
                la = ffma2(paf2[sj + 1], q.x, la);
                lb = ffma2(pbf2[sj + 1], q.x, lb);
                la = ffma2(paf2[sj + 2], q.y, la);
                lb = ffma2(pbf2[sj + 2], q.y, lb);
            }
            ull h2 = fmul2(la, lb);          // log2 units
            float h0, h1;
            unpack2(h0, h1, h2);

            float dd0 = h0 - M0, dd1 = h1 - M1;
            float q0 = ex2(-fabsf(dd0)), q1 = ex2(-fabsf(dd1));
            bool g0 = dd0 > 0.f, g1 = dd1 > 0.f;
            float r0 = g0 ? q0 : 1.f, e0 = g0 ? 1.f : q0;
            float r1 = g1 ? q1 : 1.f, e1 = g1 ? 1.f : q1;
            M0 = fmaxf(M0, h0);
            M1 = fmaxf(M1, h1);
            ull r2 = pack2(r0, r1), e2 = pack2(e0, e1);
            D2 = ffma2(D2, r2, e2);
            A0 = ffma2(A0, r2, fmul2(e2, *(const ull*)&smX[0][2*nn]));
            A1 = ffma2(A1, r2, fmul2(e2, *(const ull*)&smX[1][2*nn]));
            A2 = ffma2(A2, r2, fmul2(e2, *(const ull*)&smX[2][2*nn]));
        }

        // ---- phase 1 for next tile ----
        if (tile + 1 < TPC) {
            const int n = s * (TPC * TILE) + (tile + 1) * TILE + t;
            float xn0 = x[3*n], xn1 = x[3*n+1], xn2 = x[3*n+2];
            float vn2 = fmaf(xn0, xn0, fmaf(xn1, xn1, xn2 * xn2));
            float v = sqrtf(vn2);
            float d2 = um2 + vn2 - 2.f * fmaf(xm0, xn0, fmaf(xm1, xn1, xm2 * xn2));
            float d = sqrtf(fmaxf(d2, 0.f));
            float v2 = v * v, v3 = v2 * v, v4 = v2 * v2;
            float dd2 = d * d, dd3 = dd2 * d, dd4 = dd2 * dd2;
            __syncthreads();
            const int pr = t >> 1, ln = t & 1;
            smP[pr][0][ln]  = v;      smP[pr][1][ln]  = v2;
            smP[pr][2][ln]  = v3;     smP[pr][3][ln]  = v4;
            smP[pr][4][ln]  = d;      smP[pr][5][ln]  = d*v;
            smP[pr][6][ln]  = d*v2;   smP[pr][7][ln]  = d*v3;
            smP[pr][8][ln]  = dd2;    smP[pr][9][ln]  = dd2*v;
            smP[pr][10][ln] = dd2*v2; smP[pr][11][ln] = dd3;
            smP[pr][12][ln] = dd3*v;  smP[pr][13][ln] = dd4;
            smX[0][t] = xn0; smX[1][t] = xn1; smX[2][t] = xn2;
            __syncthreads();
        }
    }

    // ---- epilogue: merge even/odd lanes, write per-split raw stats ----
    float D0, D1, a00, a10, a01, a11, a02, a12;
    unpack2(D0, D1, D2);
    unpack2(a00, a10, A0);
    unpack2(a01, a11, A1);
    unpack2(a02, a12, A2);
    float Mx = fmaxf(M0, M1);
    float r0 = ex2(M0 - Mx);
    float r1 = ex2(M1 - Mx);
    g_part[m][s][0][t] = Mx;              // log2 units
    g_part[m][s][1][t] = fmaf(D0, r0, D1 * r1);
    g_part[m][s][2][t] = fmaf(a00, r0, a10 * r1);
    g_part[m][s][3][t] = fmaf(a01, r0, a11 * r1);
    g_part[m][s][4][t] = fmaf(a02, r0, a12 * r1);
}

// ---------------------------------------------------------------------------
// ReduceA: merge the 2 splits per m (max-rescaled, log2 units), normalize,
// partial-sum over a 16-m block. grid=RBLK, block=128. Deterministic.
// ---------------------------------------------------------------------------
__global__ void __launch_bounds__(128) reduceA_kernel()
{
    const int c = threadIdx.x;
    const int m0 = blockIdx.x * (NP / RBLK);
    float s0 = 0.f, s1 = 0.f, s2 = 0.f;
    #pragma unroll 4
    for (int m = m0; m < m0 + NP / RBLK; ++m) {
        float Ma = g_part[m][0][0][c], Mb = g_part[m][1][0][c];
        float Mm = fmaxf(Ma, Mb);
        float ra = ex2(Ma - Mm), rb = ex2(Mb - Mm);
        float D  = fmaf(g_part[m][0][1][c], ra, g_part[m][1][1][c] * rb);
        float A0 = fmaf(g_part[m][0][2][c], ra, g_part[m][1][2][c] * rb);
        float A1 = fmaf(g_part[m][0][3][c], ra, g_part[m][1][3][c] * rb);
        float A2 = fmaf(g_part[m][0][4][c], ra, g_part[m][1][4][c] * rb);
        float inv = 1.f / D;
        s0 = fmaf(A0, inv, s0);
        s1 = fmaf(A1, inv, s1);
        s2 = fmaf(A2, inv, s2);
    }
    g_red[0][blockIdx.x][c] = s0;
    g_red[1][blockIdx.x][c] = s1;
    g_red[2][blockIdx.x][c] = s2;
}

// ---------------------------------------------------------------------------
// ReduceB: single CTA sums g_red (73KB, high MLP), applies Wf, tree-reduces
// over channels, emits the 9 output floats. Deterministic.
// ---------------------------------------------------------------------------
__global__ void __launch_bounds__(128) reduceB_kernel(const float* __restrict__ x,
                                                      const float* __restrict__ Wf,
                                                      float* __restrict__ out)
{
    __shared__ float red[6][CC];
    const int c = threadIdx.x;
    float s0 = 0.f, s1 = 0.f, s2 = 0.f;
    #pragma unroll
    for (int b = 0; b < RBLK; ++b) {
        s0 += g_red[0][b][c];
        s1 += g_red[1][b][c];
        s2 += g_red[2][b][c];
    }
    float w0 = Wf[c], w1 = Wf[CC + c];
    red[0][c] = w0 * s0; red[1][c] = w0 * s1; red[2][c] = w0 * s2;
    red[3][c] = w1 * s0; red[4][c] = w1 * s1; red[5][c] = w1 * s2;
    __syncthreads();
    for (int off = 64; off > 0; off >>= 1) {
        if (c < off) {
            #pragma unroll
            for (int q = 0; q < 6; ++q) red[q][c] += red[q][c + off];
        }
        __syncthreads();
    }
    if (c < 3) out[c] = x[c];             // row 0 = x[0, 0, :]
    if (c == 0) {
        #pragma unroll
        for (int q = 0; q < 6; ++q) out[3 + q] = red[q][0];
    }
}

extern "C" void kernel_launch(void* const* d_in, const int* in_sizes, int n_in,
                              void* d_out, int out_size)
{
    const float* x   = (const float*)d_in[0];
    const float* Wa1 = (const float*)d_in[1];
    const float* ba1 = (const float*)d_in[2];
    const float* Wb1 = (const float*)d_in[3];
    const float* bb1 = (const float*)d_in[4];
    const float* Wa2 = (const float*)d_in[5];
    const float* ba2 = (const float*)d_in[6];
    const float* Wb2 = (const float*)d_in[7];
    const float* bb2 = (const float*)d_in[8];
    const float* Wa3 = (const float*)d_in[9];
    const float* ba3 = (const float*)d_in[10];
    const float* Wb3 = (const float*)d_in[11];
    const float* bb3 = (const float*)d_in[12];
    const float* Wf  = (const float*)d_in[13];

    precompA_kernel<<<1, 128>>>(Wa1, ba1, Wb1, bb1, Wa2, ba2, Wb2, bb2);
    precompB_kernel<<<35, 256>>>(Wa3, ba3, Wb3, bb3);
    dim3 grid(NP, NSPLIT);
    fps_main_kernel<<<grid, 128>>>(x);
    reduceA_kernel<<<RBLK, 128>>>();
    reduceB_kernel<<<1, 128>>>(x, Wf, (float*)d_out);
}